// round 17
// baseline (speedup 1.0000x reference)
#include <cuda_runtime.h>
#include <cuda_bf16.h>

// Problem constants (from reference)
#define C_L0 0.05f
#define C_D  0.0075f
#define C_DS 0.005f

#define TPB 256                // batch elems per chunk == threads per block
#define WSLICE4 (32 * 14 / 4)  // float4s per warp slice per row (112)
#define ROWF (TPB * 14)        // floats per staged time-row (3584)

// Closed-form trajectory: with (ux,uy) constant (both segments use
// actions[:,0:3] due to the reference's end-of-loop update quirk), the ODE is
// linear with constant generator w_hat, axis w=(ux,uy,0):
//   R(s) = I + sin(th)/w * w_hat + (1-cos th)/w^2 * w_hat^2,  th = |w| s
//   r(s) = ( (1-cos th)/w^2 * uy, -(1-cos th)/w^2 * ux, s - (th - sin th)/|w| )
// Row (seg,t) = state after n_eff = seg*nsteps + min(t,nsteps) steps (frozen
// beyond nsteps by the reference's masking). Deviation from RK4 ~1e-5 abs,
// far under the 1e-3 tolerance.
//
// PERSISTENT single-wave kernel: grid = SMs x resident-CTAs (one full wave,
// no wave-quantization tail). Work = nchunks*2T row-units, partitioned
// contiguously in chunk-major order -> each CTA spans <=2 batch chunks, so
// actions are loaded at most twice per CTA. Warp-autonomous staging/drain
// (no block barriers): stage 32-elem slice in smem, __syncwarp, float4 drain.
__global__ void __launch_bounds__(TPB, 8)
ode_forward_kernel(const float* __restrict__ act, float* __restrict__ out,
                   int B, int T, int nchunks) {
    __shared__ __align__(16) float sbuf[ROWF];

    int wid  = threadIdx.x >> 5;
    int lane = threadIdx.x & 31;

    int T2 = 2 * T;
    long long nwork = (long long)nchunks * T2;
    long long u0 = (long long)blockIdx.x * nwork / gridDim.x;
    long long u1 = (long long)(blockIdx.x + 1) * nwork / gridDim.x;

    // Warp-private smem slice (output-linear within the chunk's row image).
    float2* srow = (float2*)&sbuf[(size_t)threadIdx.x * 14];
    const float4* wslice4 = (const float4*)&sbuf[(size_t)wid * 32 * 14];

    int cur_chunk = -1;
    float ux = 0.f, uy = 0.f, w = 0.f, w2 = 0.f, inv_w2 = 0.f, uxuy = 0.f;
    int nsteps = 0;
    bool active = false, wfull = false;
    int wb0 = 0, wvalid = 0;

    for (long long u = u0; u < u1; u++) {
        int chunk = (int)(u / T2);
        int row   = (int)(u - (long long)chunk * T2);

        if (chunk != cur_chunk) {
            cur_chunk = chunk;
            int b0 = chunk * TPB;
            int b  = b0 + threadIdx.x;
            active = (b < B);
            wb0    = b0 + wid * 32;
            wvalid = min(32, max(0, B - wb0));
            wfull  = (wvalid == 32);

            float a0 = 0.f, a1 = 0.f, a2 = 0.f;
            if (active) {
                a0 = __ldg(&act[(size_t)b * 6 + 0]);
                a1 = __ldg(&act[(size_t)b * 6 + 1]);
                a2 = __ldg(&act[(size_t)b * 6 + 2]);
            }
            float l = C_L0 + a0;
            ux = a2 / (-(l * C_D));
            uy = a1 / (l * C_D);
            nsteps = min((int)floorf(l / C_DS), T - 1);
            w2 = fmaf(ux, ux, uy * uy);
            w  = sqrtf(w2);
            inv_w2 = 1.f / w2;        // actions ~U(0,1)*0.01 -> w >> 0 generically
            uxuy = ux * uy;
        }

        int seg = (row >= T) ? 1 : 0;
        int t   = row - seg * T;
        int n_eff = seg * nsteps + min(t, nsteps);
        float s = (float)n_eff * C_DS;

        float th = w * s;
        float sth, cth;
        __sincosf(th, &sth, &cth);

        float A, Bc, Cz;              // sin/w, (1-cos)/w^2, (th-sin)/w^3
        if (th > 1e-3f) {
            A  = sth * (w * inv_w2);
            Bc = (1.f - cth) * inv_w2;
            Cz = (th - sth) * inv_w2 * (w * inv_w2);
        } else {                      // Taylor fallback (tiny/zero angle)
            float t2 = th * th;
            A  = s * (1.f - t2 * (1.f / 6.f));
            Bc = 0.5f * s * s * (1.f - t2 * (1.f / 12.f));
            Cz = s * s * s * (1.f / 6.f) * (1.f - t2 * (1.f / 20.f));
            cth = 1.f - 0.5f * t2;
        }

        // Protect previous row's drain reads before re-staging (warp-local).
        __syncwarp();

        if (active) {
            srow[0] = make_float2(Bc * uy,        -Bc * ux);            // r.x, r.y
            srow[1] = make_float2(s - Cz * w2,    1.f - Bc * uy * uy);  // r.z, R00
            srow[2] = make_float2(Bc * uxuy,      A * uy);              // R01, R02
            srow[3] = make_float2(Bc * uxuy,      1.f - Bc * ux * ux);  // R10, R11
            srow[4] = make_float2(-A * ux,        -A * uy);             // R12, R20
            srow[5] = make_float2(A * ux,         cth);                 // R21, R22
            srow[6] = make_float2(ux,             uy);
        }
        __syncwarp();   // warp's slice staged

        // Drain warp slice: 112 float4 = 3*32 + 16, contiguous in gmem.
        size_t base = ((size_t)row * (size_t)B + (size_t)wb0) * 14;
        if (wfull) {
            float4* o4 = (float4*)(out + base);
#pragma unroll
            for (int i = 0; i < 3; i++)
                __stcs(&o4[lane + i * 32], wslice4[lane + i * 32]);
            if (lane < (WSLICE4 - 96))
                __stcs(&o4[lane + 96], wslice4[lane + 96]);
        } else if (wvalid > 0) {
            const float* ws = (const float*)wslice4;
            int rowfloats = wvalid * 14;
            for (int f = lane; f < rowfloats; f += 32)
                out[base + f] = ws[f];
        }
    }
}

extern "C" void kernel_launch(void* const* d_in, const int* in_sizes, int n_in,
                              void* d_out, int out_size) {
    const float* actions = (const float*)d_in[0];
    float* out = (float*)d_out;

    int B = in_sizes[0] / 6;                 // 262144
    int T = out_size / (2 * B * 14);         // time steps per segment (incl. t=0)
    int nchunks = (B + TPB - 1) / TPB;       // 1024

    // One full wave: SMs x resident CTAs (pure host queries; capture-safe).
    int dev = 0, nsm = 148, perSM = 8;
    cudaGetDevice(&dev);
    cudaDeviceGetAttribute(&nsm, cudaDevAttrMultiProcessorCount, dev);
    cudaOccupancyMaxActiveBlocksPerMultiprocessor(&perSM, ode_forward_kernel, TPB, 0);
    if (perSM < 1) perSM = 1;
    long long nwork = (long long)nchunks * 2 * T;
    long long grid = (long long)nsm * perSM;
    if (grid > nwork) grid = nwork;

    ode_forward_kernel<<<(int)grid, TPB>>>(actions, out, B, T, nchunks);
}